// round 2
// baseline (speedup 1.0000x reference)
#include <cuda_runtime.h>
#include <cstdint>

// ToRGB: out[b,co,y,x] = sum_c sum_{ky,kx} in[b,c,y-1+ky,x-1+kx] * w[co,c,ky,kx]*scale
//                        + bias[co] + upfirdn2x(skip)[b,co,y,x]
// Shapes: in [8,512,128,128] f32, skip [8,3,64,64] f32, w [3,512,3,3] f32, bias [3] f32.
// Strategy: HBM-stream input via cp.async 3-stage ring; per-CTA: 1 batch x 8 rows x 128 cols;
// compute with packed fma.rn.f32x2 (2 x-pixels per FMA). Weights duplicated to f32x2 in smem.

constexpr int TPB       = 256;
constexpr int C_IN      = 512;
constexpr int HW        = 128;
constexpr int TILE_W    = 132;                 // cols 0..127 data, 128..131 zeros (halo)
constexpr int TILE_ROWS = 10;                  // y0-1 .. y0+8
constexpr int TILE_FLOATS = TILE_ROWS * TILE_W; // 1320
constexpr int CPS       = 4;                   // channels per stage
constexpr int NSTAGE    = 3;
constexpr int WSTRIDE   = 28;                  // ull per channel (27 weights, padded)
constexpr unsigned WDUP_BYTES  = (unsigned)C_IN * WSTRIDE * 8;              // 114688
constexpr unsigned TILES_BYTES = (unsigned)NSTAGE * CPS * TILE_FLOATS * 4;  // 63360
constexpr unsigned SMEM_BYTES  = WDUP_BYTES + TILES_BYTES;                  // 178048

using ull = unsigned long long;

__device__ __forceinline__ ull pack2(float lo, float hi) {
    ull r; asm("mov.b64 %0, {%1,%2};" : "=l"(r) : "f"(lo), "f"(hi)); return r;
}
__device__ __forceinline__ void unpack2(ull v, float& lo, float& hi) {
    asm("mov.b64 {%0,%1}, %2;" : "=f"(lo), "=f"(hi) : "l"(v));
}
__device__ __forceinline__ void ffma2(ull& d, ull a, ull b) {
    asm("fma.rn.f32x2 %0, %1, %2, %0;" : "+l"(d) : "l"(a), "l"(b));
}
__device__ __forceinline__ void cp16(uint32_t dst, const float* src, int ssz) {
    asm volatile("cp.async.cg.shared.global [%0], [%1], 16, %2;"
                 :: "r"(dst), "l"(src), "r"(ssz) : "memory");
}
__device__ __forceinline__ void cp_commit() {
    asm volatile("cp.async.commit_group;" ::: "memory");
}
template<int N> __device__ __forceinline__ void cp_wait() {
    asm volatile("cp.async.wait_group %0;" :: "n"(N) : "memory");
}

__global__ void __launch_bounds__(TPB, 1)
torgb_kernel(const float* __restrict__ input, const float* __restrict__ skip,
             const float* __restrict__ weight, const float* __restrict__ bias,
             float* __restrict__ out)
{
    extern __shared__ char smem_raw[];
    ull*   wdup  = reinterpret_cast<ull*>(smem_raw);
    float* tiles = reinterpret_cast<float*>(smem_raw + WDUP_BYTES);

    const int tid = threadIdx.x;
    const int tx  = tid & 63;   // x-pair index: pixels (2tx, 2tx+1)
    const int tyq = tid >> 6;   // 0..3, rows y0+2*tyq, +1
    const int b   = blockIdx.y;
    const int y0  = blockIdx.x * 8;

    // ---- preload weights * scale, duplicated into f32x2 lanes ----
    const float scale = 1.0f / sqrtf(4608.0f);   // 1/sqrt(C*3*3)
    for (int i = tid; i < 3 * C_IN * 9; i += TPB) {
        float w = weight[i] * scale;
        int co = i / (C_IN * 9);
        int c  = (i / 9) % C_IN;
        int k  = i % 9;
        wdup[c * WSTRIDE + co * 9 + k] = pack2(w, w);
    }
    // ---- zero halo cols 128..131 of every tile row (written once) ----
    for (int i = tid; i < NSTAGE * CPS * TILE_ROWS; i += TPB) {
        float* row = tiles + i * TILE_W;
        row[128] = 0.f; row[129] = 0.f; row[130] = 0.f; row[131] = 0.f;
    }

    // ---- per-thread cp.async chunk descriptors (5 x 16B per stage) ----
    uint32_t tiles_u32 = (uint32_t)__cvta_generic_to_shared(tiles);
    int dsto[5], srco[5], ssz[5];
#pragma unroll
    for (int j = 0; j < 5; j++) {
        int g   = j * TPB + tid;     // 0..1279 over (4 channels x 10 rows x 32 float4)
        int ch  = g / 320;
        int rem = g - ch * 320;
        int row = rem >> 5;
        int c4  = rem & 31;
        int y   = y0 - 1 + row;
        bool ok = (y >= 0) && (y < HW);
        dsto[j] = (ch * TILE_FLOATS + row * TILE_W + c4 * 4) * 4;   // bytes
        srco[j] = ch * (HW * HW) + (ok ? y : 0) * HW + c4 * 4;      // floats
        ssz[j]  = ok ? 16 : 0;                                      // zfill OOB rows
    }
    const float* in_b = input + (size_t)b * C_IN * HW * HW;

    __syncthreads();  // wdup + halo zeros visible before any compute

    // ---- prologue: fill all 3 stages ----
#pragma unroll
    for (int s = 0; s < NSTAGE; s++) {
        uint32_t sb = tiles_u32 + s * (CPS * TILE_FLOATS * 4);
        const float* src_c = in_b + (size_t)(s * CPS) * HW * HW;
#pragma unroll
        for (int j = 0; j < 5; j++) cp16(sb + dsto[j], src_c + srco[j], ssz[j]);
        cp_commit();
    }

    ull acc[6];   // [co][dy] f32x2 over x-pair
#pragma unroll
    for (int i = 0; i < 6; i++) acc[i] = 0ull;

    const int col_left  = (tx == 0) ? 131 : 2 * tx - 1;   // 131 holds zero
    const int col_right = 2 * tx + 2;                     // col 128 holds zero
    const int trow0     = tyq * 2;

    int s = 0;
    for (int it = 0; it < C_IN / CPS; it++) {
        cp_wait<NSTAGE - 1>();
        __syncthreads();
        const float* st  = tiles + s * (CPS * TILE_FLOATS);
        const ull*   wcb = wdup + (it * CPS) * WSTRIDE;
#pragma unroll
        for (int ci = 0; ci < CPS; ci++) {
            const float* tp = st + ci * TILE_FLOATS + trow0 * TILE_W;
            ull P[4], A[4], Cc[4];
#pragma unroll
            for (int r = 0; r < 4; r++) {
                const float* rp = tp + r * TILE_W;
                float2 v = *reinterpret_cast<const float2*>(rp + 2 * tx);
                float L = rp[col_left];
                float R = rp[col_right];
                P[r]  = pack2(v.x, v.y);   // tap kx=1
                A[r]  = pack2(L,   v.x);   // tap kx=0
                Cc[r] = pack2(v.y, R);     // tap kx=2
            }
            const ull* w = wcb + ci * WSTRIDE;
#pragma unroll
            for (int co = 0; co < 3; co++)
#pragma unroll
                for (int ky = 0; ky < 3; ky++) {
                    ull w0 = w[co * 9 + ky * 3 + 0];
                    ull w1 = w[co * 9 + ky * 3 + 1];
                    ull w2 = w[co * 9 + ky * 3 + 2];
#pragma unroll
                    for (int dy = 0; dy < 2; dy++) {
                        int r = dy + ky;
                        ffma2(acc[co * 2 + dy], w0, A[r]);
                        ffma2(acc[co * 2 + dy], w1, P[r]);
                        ffma2(acc[co * 2 + dy], w2, Cc[r]);
                    }
                }
        }
        __syncthreads();
        int nc = (it + NSTAGE) * CPS;
        if (nc < C_IN) {
            uint32_t sb = tiles_u32 + s * (CPS * TILE_FLOATS * 4);
            const float* src_c = in_b + (size_t)nc * HW * HW;
#pragma unroll
            for (int j = 0; j < 5; j++) cp16(sb + dsto[j], src_c + srco[j], ssz[j]);
        }
        cp_commit();   // commit (possibly empty) keeps group accounting uniform
        s++; if (s == NSTAGE) s = 0;
    }
    cp_wait<0>();

    // ---- epilogue: bias + 2x blur-upsampled skip, write float2 ----
    // Per dim: near tap 3/4 at s=y>>1, far tap 1/4 at s +/- 1 (parity), OOB -> 0.
    const float* skb = skip + (size_t)b * 3 * 64 * 64;
#pragma unroll
    for (int co = 0; co < 3; co++) {
        float bs = bias[co];
        const float* sk = skb + co * 64 * 64;
#pragma unroll
        for (int dy = 0; dy < 2; dy++) {
            int y   = y0 + tyq * 2 + dy;
            int syn = y >> 1;
            int syf = (y & 1) ? syn + 1 : syn - 1;
            float wyf = (syf >= 0 && syf < 64) ? 0.25f : 0.0f;
            int syfc = min(63, max(0, syf));
            const float* rn = sk + syn * 64;
            const float* rf = sk + syfc * 64;
            float cl_n = (tx > 0)  ? rn[tx - 1] : 0.f;
            float cc_n = rn[tx];
            float cr_n = (tx < 63) ? rn[tx + 1] : 0.f;
            float cl_f = (tx > 0)  ? rf[tx - 1] : 0.f;
            float cc_f = rf[tx];
            float cr_f = (tx < 63) ? rf[tx + 1] : 0.f;
            // x0 = 2tx (even): near col tx (3/4), far col tx-1 (1/4)
            // x1 = 2tx+1 (odd): near col tx (3/4), far col tx+1 (1/4)
            float rnx0 = 0.75f * cc_n + 0.25f * cl_n;
            float rnx1 = 0.75f * cc_n + 0.25f * cr_n;
            float rfx0 = 0.75f * cc_f + 0.25f * cl_f;
            float rfx1 = 0.75f * cc_f + 0.25f * cr_f;
            float sx0 = 0.75f * rnx0 + wyf * rfx0;
            float sx1 = 0.75f * rnx1 + wyf * rfx1;

            float lo, hi; unpack2(acc[co * 2 + dy], lo, hi);
            float2 o;
            o.x = lo + bs + sx0;
            o.y = hi + bs + sx1;
            *reinterpret_cast<float2*>(
                out + (((size_t)(b * 3 + co) * HW + y) * HW) + 2 * tx) = o;
        }
    }
}

extern "C" void kernel_launch(void* const* d_in, const int* in_sizes, int n_in,
                              void* d_out, int out_size)
{
    const float* input  = (const float*)d_in[0];  // [8,512,128,128]
    const float* skip   = (const float*)d_in[1];  // [8,3,64,64]
    const float* weight = (const float*)d_in[2];  // [3,512,3,3]
    const float* bias   = (const float*)d_in[3];  // [3]
    float* out = (float*)d_out;                   // [8,3,128,128]

    cudaFuncSetAttribute(torgb_kernel,
                         cudaFuncAttributeMaxDynamicSharedMemorySize, SMEM_BYTES);
    dim3 grid(16, 8);   // 16 y-tiles of 8 rows, 8 batches
    torgb_kernel<<<grid, TPB, SMEM_BYTES>>>(input, skip, weight, bias, out);
}

// round 3
// speedup vs baseline: 1.0737x; 1.0737x over previous
#include <cuda_runtime.h>
#include <cstdint>

// ToRGB split-K conv + epilogue.
// k0: expand weight*scale into duplicated-f32x2 global table g_wdup.
// k1: conv, grid (16,8,4): z = channel quarter (128 ch). cp.async ring streams
//     data (4ch x 10rows) + that quarter's weights per stage. Partial sums -> g_part.
// k2: out = sum(g_part[0..3]) + bias + upfirdn2x(skip).

using ull = unsigned long long;

constexpr int TPB      = 256;
constexpr int HW       = 128;
constexpr int C_IN     = 512;
constexpr int C_PER    = 128;                  // channels per CTA (quarter)
constexpr int CPS      = 4;                    // channels per stage
constexpr int NSTAGE   = 3;
constexpr int NITER    = C_PER / CPS;          // 32
constexpr int TILE_W   = 136;                  // idx = col + 4; zeros at 0..3, 132..135
constexpr int TILE_ROWS= 10;
constexpr int TILE_FLOATS = TILE_ROWS * TILE_W;       // 1360
constexpr int DATA_BYTES  = CPS * TILE_FLOATS * 4;    // 21760
constexpr int WSTAGE_BYTES= CPS * 28 * 8;             // 896
constexpr int STAGE_BYTES = DATA_BYTES + WSTAGE_BYTES;// 22656
constexpr unsigned SMEM_BYTES = NSTAGE * STAGE_BYTES; // 67968
constexpr int NCHUNK   = CPS * TILE_ROWS * 32 + CPS * 14;  // 1280 data + 56 weight = 1336
constexpr int JMAX     = (NCHUNK + TPB - 1) / TPB;         // 6

__device__ __align__(16) ull   g_wdup[C_IN * 28];          // duplicated weights*scale
__device__ float g_part[4][8 * 3 * HW * HW];               // split-K partials

__device__ __forceinline__ ull pack2(float lo, float hi) {
    ull r; asm("mov.b64 %0, {%1,%2};" : "=l"(r) : "f"(lo), "f"(hi)); return r;
}
__device__ __forceinline__ void unpack2(ull v, float& lo, float& hi) {
    asm("mov.b64 {%0,%1}, %2;" : "=f"(lo), "=f"(hi) : "l"(v));
}
__device__ __forceinline__ void ffma2(ull& d, ull a, ull b) {
    asm("fma.rn.f32x2 %0, %1, %2, %0;" : "+l"(d) : "l"(a), "l"(b));
}
__device__ __forceinline__ void cp16(uint32_t dst, const void* src, int ssz) {
    asm volatile("cp.async.cg.shared.global [%0], [%1], 16, %2;"
                 :: "r"(dst), "l"(src), "r"(ssz) : "memory");
}
__device__ __forceinline__ void cp_commit() {
    asm volatile("cp.async.commit_group;" ::: "memory");
}
template<int N> __device__ __forceinline__ void cp_wait() {
    asm volatile("cp.async.wait_group %0;" :: "n"(N) : "memory");
}

// ---------------- k0: weight prep ----------------
__global__ void prep_kernel(const float* __restrict__ weight)
{
    int i = blockIdx.x * TPB + threadIdx.x;
    if (i >= 3 * C_IN * 9) return;
    float w = weight[i] * (1.0f / sqrtf(4608.0f));
    int co = i / (C_IN * 9);
    int c  = (i / 9) % C_IN;
    int k  = i % 9;
    g_wdup[c * 28 + co * 9 + k] = pack2(w, w);
}

// ---------------- k1: split-K conv ----------------
__global__ void __launch_bounds__(TPB, 2)
conv_kernel(const float* __restrict__ input)
{
    extern __shared__ char smem_raw[];
    float* tiles = reinterpret_cast<float*>(smem_raw);

    const int tid = threadIdx.x;
    const int tx  = tid & 63;          // x-pair: pixels (2tx, 2tx+1)
    const int tyq = tid >> 6;          // rows y0 + 2*tyq + {0,1}
    const int b   = blockIdx.y;
    const int y0  = blockIdx.x * 8;
    const int qh  = blockIdx.z;        // channel quarter
    const int cbase = qh * C_PER;

    // zero halo columns (idx 0..3, 132..135) for every (stage, ch, row)
    for (int i = tid; i < NSTAGE * CPS * TILE_ROWS; i += TPB) {
        float4* row = reinterpret_cast<float4*>(tiles + (i / (CPS*TILE_ROWS)) * (STAGE_BYTES/4)
                                                + (i % (CPS*TILE_ROWS)) * TILE_W);
        row[0] = make_float4(0.f,0.f,0.f,0.f);
        *reinterpret_cast<float4*>(reinterpret_cast<float*>(row) + 132) = make_float4(0.f,0.f,0.f,0.f);
    }

    // per-thread cp.async chunk descriptors
    uint32_t tiles_u32 = (uint32_t)__cvta_generic_to_shared(tiles);
    int dsto[JMAX], boff[JMAX], ssz[JMAX];
    bool isw[JMAX], act[JMAX];
#pragma unroll
    for (int j = 0; j < JMAX; j++) {
        int g = j * TPB + tid;
        act[j] = (g < NCHUNK);
        isw[j] = false; dsto[j] = 0; boff[j] = 0; ssz[j] = 0;
        if (g < CPS * TILE_ROWS * 32) {              // data chunk
            int ch  = g / (TILE_ROWS * 32);
            int rem = g - ch * (TILE_ROWS * 32);
            int row = rem >> 5;
            int c4  = rem & 31;
            int y   = y0 - 1 + row;
            bool ok = (y >= 0) && (y < HW);
            dsto[j] = ch * (TILE_FLOATS * 4) + row * (TILE_W * 4) + 16 + c4 * 16;
            boff[j] = ch * (HW * HW * 4) + (ok ? y : 0) * (HW * 4) + c4 * 16;
            ssz[j]  = ok ? 16 : 0;
        } else if (act[j]) {                          // weight chunk
            int wq = g - CPS * TILE_ROWS * 32;
            int ch = wq / 14, p = wq % 14;
            dsto[j] = DATA_BYTES + ch * 224 + p * 16;
            boff[j] = ch * 224 + p * 16;
            ssz[j]  = 16;
            isw[j]  = true;
        }
    }
    const char* in_b = reinterpret_cast<const char*>(input) + (size_t)b * C_IN * HW * HW * 4;
    const char* wgl  = reinterpret_cast<const char*>(g_wdup);

    __syncthreads();   // halo zeros visible

    // prologue: fill all stages
#pragma unroll
    for (int s = 0; s < NSTAGE; s++) {
        uint32_t sb = tiles_u32 + s * STAGE_BYTES;
        int bc = cbase + s * CPS;
        const char* db = in_b + (size_t)bc * (HW * HW * 4);
        const char* wb = wgl + (size_t)bc * 224;
#pragma unroll
        for (int j = 0; j < JMAX; j++)
            if (act[j]) cp16(sb + dsto[j], (isw[j] ? wb : db) + boff[j], ssz[j]);
        cp_commit();
    }

    ull acc[6];
#pragma unroll
    for (int i = 0; i < 6; i++) acc[i] = 0ull;

    const int trow0 = tyq * 2;
    int s = 0;
    for (int it = 0; it < NITER; it++) {
        cp_wait<NSTAGE - 1>();
        __syncthreads();
        const float* st = tiles + s * (STAGE_BYTES / 4);
        const ull*   sw = reinterpret_cast<const ull*>(reinterpret_cast<const char*>(st) + DATA_BYTES);
#pragma unroll
        for (int ci = 0; ci < CPS; ci++) {
            const float* tp = st + ci * TILE_FLOATS + trow0 * TILE_W;
            ull P[4], A[4], Cc[4];
#pragma unroll
            for (int r = 0; r < 4; r++) {
                const float* rp = tp + r * TILE_W;
                float2 l = *reinterpret_cast<const float2*>(rp + 2 * tx + 2);
                float2 c = *reinterpret_cast<const float2*>(rp + 2 * tx + 4);
                float2 rr= *reinterpret_cast<const float2*>(rp + 2 * tx + 6);
                P[r]  = pack2(c.x, c.y);
                A[r]  = pack2(l.y, c.x);
                Cc[r] = pack2(c.y, rr.x);
            }
            const ull* w = sw + ci * 28;
#pragma unroll
            for (int co = 0; co < 3; co++)
#pragma unroll
                for (int ky = 0; ky < 3; ky++) {
                    ull w0 = w[co * 9 + ky * 3 + 0];
                    ull w1 = w[co * 9 + ky * 3 + 1];
                    ull w2 = w[co * 9 + ky * 3 + 2];
#pragma unroll
                    for (int dy = 0; dy < 2; dy++) {
                        int r = dy + ky;
                        ffma2(acc[co * 2 + dy], w0, A[r]);
                        ffma2(acc[co * 2 + dy], w1, P[r]);
                        ffma2(acc[co * 2 + dy], w2, Cc[r]);
                    }
                }
        }
        __syncthreads();
        int nc = it + NSTAGE;
        if (nc < NITER) {
            uint32_t sb = tiles_u32 + s * STAGE_BYTES;
            int bc = cbase + nc * CPS;
            const char* db = in_b + (size_t)bc * (HW * HW * 4);
            const char* wb = wgl + (size_t)bc * 224;
#pragma unroll
            for (int j = 0; j < JMAX; j++)
                if (act[j]) cp16(sb + dsto[j], (isw[j] ? wb : db) + boff[j], ssz[j]);
        }
        cp_commit();
        s++; if (s == NSTAGE) s = 0;
    }
    cp_wait<0>();

    // write partials
#pragma unroll
    for (int co = 0; co < 3; co++)
#pragma unroll
        for (int dy = 0; dy < 2; dy++) {
            int y = y0 + tyq * 2 + dy;
            float lo, hi; unpack2(acc[co * 2 + dy], lo, hi);
            float2 o; o.x = lo; o.y = hi;
            *reinterpret_cast<float2*>(
                &g_part[qh][(((size_t)(b * 3 + co) * HW + y) * HW) + 2 * tx]) = o;
        }
}

// ---------------- k2: epilogue ----------------
__global__ void __launch_bounds__(TPB)
epilogue_kernel(const float* __restrict__ skip, const float* __restrict__ bias,
                float* __restrict__ out)
{
    int id = blockIdx.x * TPB + threadIdx.x;          // one float2 (2 px)
    int xp = id & 63;
    int y  = (id >> 6) & 127;
    int p  = id >> 13;                                 // b*3+co, 0..23
    int b  = p / 3, co = p % 3;

    float2 s = make_float2(0.f, 0.f);
#pragma unroll
    for (int h = 0; h < 4; h++) {
        float2 v = reinterpret_cast<const float2*>(g_part[h])[id];
        s.x += v.x; s.y += v.y;
    }
    float bs = bias[co];

    const float* sk = skip + ((size_t)b * 3 + co) * 64 * 64;
    int syn = y >> 1;
    int syf = (y & 1) ? syn + 1 : syn - 1;
    float wyf = (syf >= 0 && syf < 64) ? 0.25f : 0.0f;
    int syfc = min(63, max(0, syf));
    const float* rn = sk + syn * 64;
    const float* rf = sk + syfc * 64;
    float cl_n = (xp > 0)  ? rn[xp - 1] : 0.f;
    float cc_n = rn[xp];
    float cr_n = (xp < 63) ? rn[xp + 1] : 0.f;
    float cl_f = (xp > 0)  ? rf[xp - 1] : 0.f;
    float cc_f = rf[xp];
    float cr_f = (xp < 63) ? rf[xp + 1] : 0.f;
    float rnx0 = 0.75f * cc_n + 0.25f * cl_n;
    float rnx1 = 0.75f * cc_n + 0.25f * cr_n;
    float rfx0 = 0.75f * cc_f + 0.25f * cl_f;
    float rfx1 = 0.75f * cc_f + 0.25f * cr_f;
    float sx0 = 0.75f * rnx0 + wyf * rfx0;
    float sx1 = 0.75f * rnx1 + wyf * rfx1;

    float2 o;
    o.x = s.x + bs + sx0;
    o.y = s.y + bs + sx1;
    reinterpret_cast<float2*>(out)[id] = o;
}

extern "C" void kernel_launch(void* const* d_in, const int* in_sizes, int n_in,
                              void* d_out, int out_size)
{
    const float* input  = (const float*)d_in[0];  // [8,512,128,128]
    const float* skip   = (const float*)d_in[1];  // [8,3,64,64]
    const float* weight = (const float*)d_in[2];  // [3,512,3,3]
    const float* bias   = (const float*)d_in[3];  // [3]
    float* out = (float*)d_out;                   // [8,3,128,128]

    cudaFuncSetAttribute(conv_kernel,
                         cudaFuncAttributeMaxDynamicSharedMemorySize, SMEM_BYTES);

    prep_kernel<<<(3 * C_IN * 9 + TPB - 1) / TPB, TPB>>>(weight);
    dim3 grid(16, 8, 4);
    conv_kernel<<<grid, TPB, SMEM_BYTES>>>(input);
    epilogue_kernel<<<(8 * 3 * HW * HW / 2) / TPB, TPB>>>(skip, bias, out);
}

// round 8
// speedup vs baseline: 1.1189x; 1.0421x over previous
#include <cuda_runtime.h>
#include <cstdint>

// ToRGB split-K conv + epilogue, R4.
// k0: weight*scale -> g_wdup, layout per channel: 3 co-blocks of 10 ull (pad), stride 32 ull.
// k1: conv, grid (16,8,4): 4-stage cp.async ring (4ch data + weights per stage),
//     one barrier per channel-iter, weights read via LDS.128, data via 3x LDS.64.
// k2: sum partials + bias + upfirdn2x(skip).

using ull = unsigned long long;

constexpr int TPB      = 256;
constexpr int HW       = 128;
constexpr int C_IN     = 512;
constexpr int C_PER    = 128;
constexpr int CPS      = 4;
constexpr int NSTAGE   = 4;
constexpr int NITER    = C_PER / CPS;                  // 32
constexpr int TILE_W   = 136;                          // idx = col + 4
constexpr int TILE_ROWS= 10;
constexpr int TILE_FLOATS = TILE_ROWS * TILE_W;        // 1360
constexpr int DATA_BYTES  = CPS * TILE_FLOATS * 4;     // 21760
constexpr int WCH_ULL     = 32;                        // 3*10 + pad
constexpr int WSTAGE_BYTES= CPS * WCH_ULL * 8;         // 1024
constexpr int STAGE_BYTES = DATA_BYTES + WSTAGE_BYTES; // 22784
constexpr unsigned SMEM_BYTES = NSTAGE * STAGE_BYTES;  // 91136
constexpr int NDATA    = CPS * TILE_ROWS * 32;         // 1280
constexpr int NCHUNK   = NDATA + CPS * 16;             // +64 weight chunks = 1344
constexpr int JMAX     = (NCHUNK + TPB - 1) / TPB;     // 6

__device__ __align__(16) ull g_wdup[C_IN * WCH_ULL];
__device__ float g_part[4][8 * 3 * HW * HW];

__device__ __forceinline__ ull pack2(float lo, float hi) {
    ull r; asm("mov.b64 %0, {%1,%2};" : "=l"(r) : "f"(lo), "f"(hi)); return r;
}
__device__ __forceinline__ void unpack2(ull v, float& lo, float& hi) {
    asm("mov.b64 {%0,%1}, %2;" : "=f"(lo), "=f"(hi) : "l"(v));
}
__device__ __forceinline__ void ffma2(ull& d, ull a, ull b) {
    asm("fma.rn.f32x2 %0, %1, %2, %0;" : "+l"(d) : "l"(a), "l"(b));
}
__device__ __forceinline__ void cp16(uint32_t dst, const void* src, int ssz) {
    asm volatile("cp.async.cg.shared.global [%0], [%1], 16, %2;"
                 :: "r"(dst), "l"(src), "r"(ssz) : "memory");
}
__device__ __forceinline__ void cp_commit() {
    asm volatile("cp.async.commit_group;" ::: "memory");
}
template<int N> __device__ __forceinline__ void cp_wait() {
    asm volatile("cp.async.wait_group %0;" :: "n"(N) : "memory");
}

// ---------------- k0: weight prep ----------------
__global__ void prep_kernel(const float* __restrict__ weight)
{
    int i = blockIdx.x * TPB + threadIdx.x;
    if (i >= C_IN * WCH_ULL) return;
    int c = i / WCH_ULL, slot = i % WCH_ULL;
    int co = slot / 10, k = slot % 10;
    float w = 0.f;
    if (co < 3 && k < 9)
        w = weight[(co * C_IN + c) * 9 + k] * (1.0f / sqrtf(4608.0f));
    g_wdup[i] = pack2(w, w);
}

// ---------------- k1: split-K conv ----------------
__global__ void __launch_bounds__(TPB, 2)
conv_kernel(const float* __restrict__ input)
{
    extern __shared__ char smem_raw[];
    float* tiles = reinterpret_cast<float*>(smem_raw);

    const int tid = threadIdx.x;
    const int tx  = tid & 63;
    const int tyq = tid >> 6;
    const int b   = blockIdx.y;
    const int y0  = blockIdx.x * 8;
    const int qh  = blockIdx.z;
    const int cbase = qh * C_PER;

    // zero halo cols (idx 0..3, 132..135) every (stage, ch, row)
    for (int i = tid; i < NSTAGE * CPS * TILE_ROWS; i += TPB) {
        float* row = tiles + (i / (CPS * TILE_ROWS)) * (STAGE_BYTES / 4)
                   + (i % (CPS * TILE_ROWS)) * TILE_W;
        *reinterpret_cast<float4*>(row)       = make_float4(0.f, 0.f, 0.f, 0.f);
        *reinterpret_cast<float4*>(row + 132) = make_float4(0.f, 0.f, 0.f, 0.f);
    }

    uint32_t tiles_u32 = (uint32_t)__cvta_generic_to_shared(tiles);
    int dsto[JMAX], boff[JMAX], ssz[JMAX];
    bool isw[JMAX], act[JMAX];
#pragma unroll
    for (int j = 0; j < JMAX; j++) {
        int g = j * TPB + tid;
        act[j] = (g < NCHUNK);
        isw[j] = false; dsto[j] = 0; boff[j] = 0; ssz[j] = 0;
        if (g < NDATA) {
            int ch  = g / (TILE_ROWS * 32);
            int rem = g - ch * (TILE_ROWS * 32);
            int row = rem >> 5;
            int c4  = rem & 31;
            int y   = y0 - 1 + row;
            bool ok = (y >= 0) && (y < HW);
            dsto[j] = ch * (TILE_FLOATS * 4) + row * (TILE_W * 4) + 16 + c4 * 16;
            boff[j] = ch * (HW * HW * 4) + (ok ? y : 0) * (HW * 4) + c4 * 16;
            ssz[j]  = ok ? 16 : 0;
        } else if (act[j]) {
            int wq = g - NDATA;
            int ch = wq >> 4, p = wq & 15;
            dsto[j] = DATA_BYTES + ch * 256 + p * 16;
            boff[j] = ch * 256 + p * 16;
            ssz[j]  = 16;
            isw[j]  = true;
        }
    }
    const char* in_b = reinterpret_cast<const char*>(input) + (size_t)b * C_IN * HW * HW * 4;
    const char* wgl  = reinterpret_cast<const char*>(g_wdup);

    __syncthreads();   // halo zeros visible

    // prologue: fill stages 0..2
#pragma unroll
    for (int s = 0; s < NSTAGE - 1; s++) {
        uint32_t sb = tiles_u32 + s * STAGE_BYTES;
        int bc = cbase + s * CPS;
        const char* db = in_b + (size_t)bc * (HW * HW * 4);
        const char* wb = wgl + (size_t)bc * 256;
#pragma unroll
        for (int j = 0; j < JMAX; j++)
            if (act[j]) cp16(sb + dsto[j], (isw[j] ? wb : db) + boff[j], ssz[j]);
        cp_commit();
    }

    ull acc[6];
#pragma unroll
    for (int i = 0; i < 6; i++) acc[i] = 0ull;

    const int trow0 = tyq * 2;
    for (int it = 0; it < NITER; it++) {
        cp_wait<NSTAGE - 2>();
        __syncthreads();   // stage it ready; all warps done computing stage it-1

        // issue loads for it+3 into the stage consumed at it-1
        int nc = it + NSTAGE - 1;
        if (nc < NITER) {
            uint32_t sb = tiles_u32 + (nc & (NSTAGE - 1)) * STAGE_BYTES;
            int bc = cbase + nc * CPS;
            const char* db = in_b + (size_t)bc * (HW * HW * 4);
            const char* wb = wgl + (size_t)bc * 256;
#pragma unroll
            for (int j = 0; j < JMAX; j++)
                if (act[j]) cp16(sb + dsto[j], (isw[j] ? wb : db) + boff[j], ssz[j]);
        }
        cp_commit();

        const float* st = tiles + (it & (NSTAGE - 1)) * (STAGE_BYTES / 4);
#pragma unroll
        for (int ci = 0; ci < CPS; ci++) {
            const float* tp = st + ci * TILE_FLOATS + trow0 * TILE_W;
            ull P[4], A[4], Cc[4];
#pragma unroll
            for (int r = 0; r < 4; r++) {
                const float* rp = tp + r * TILE_W;
                float2 l = *reinterpret_cast<const float2*>(rp + 2 * tx + 2);
                ull    c = *reinterpret_cast<const ull*>  (rp + 2 * tx + 4);
                float2 rr= *reinterpret_cast<const float2*>(rp + 2 * tx + 6);
                float clo, chi; unpack2(c, clo, chi);
                P[r]  = c;
                A[r]  = pack2(l.y, clo);
                Cc[r] = pack2(chi, rr.x);
            }
            const ulonglong2* wch = reinterpret_cast<const ulonglong2*>(
                reinterpret_cast<const char*>(st) + DATA_BYTES + ci * 256);
#pragma unroll
            for (int co = 0; co < 3; co++) {
                ulonglong2 p0 = wch[co * 5 + 0];
                ulonglong2 p1 = wch[co * 5 + 1];
                ulonglong2 p2 = wch[co * 5 + 2];
                ulonglong2 p3 = wch[co * 5 + 3];
                ulonglong2 p4 = wch[co * 5 + 4];
                ull wk[9] = { p0.x, p0.y, p1.x, p1.y, p2.x, p2.y, p3.x, p3.y, p4.x };
#pragma unroll
                for (int ky = 0; ky < 3; ky++)
#pragma unroll
                    for (int dy = 0; dy < 2; dy++) {
                        int r = dy + ky;
                        ffma2(acc[co * 2 + dy], wk[ky * 3 + 0], A[r]);
                        ffma2(acc[co * 2 + dy], wk[ky * 3 + 1], P[r]);
                        ffma2(acc[co * 2 + dy], wk[ky * 3 + 2], Cc[r]);
                    }
            }
        }
    }
    cp_wait<0>();

#pragma unroll
    for (int co = 0; co < 3; co++)
#pragma unroll
        for (int dy = 0; dy < 2; dy++) {
            int y = y0 + tyq * 2 + dy;
            float lo, hi; unpack2(acc[co * 2 + dy], lo, hi);
            float2 o; o.x = lo; o.y = hi;
            *reinterpret_cast<float2*>(
                &g_part[qh][(((size_t)(b * 3 + co) * HW + y) * HW) + 2 * tx]) = o;
        }
}

// ---------------- k2: epilogue ----------------
__global__ void __launch_bounds__(TPB)
epilogue_kernel(const float* __restrict__ skip, const float* __restrict__ bias,
                float* __restrict__ out)
{
    int id = blockIdx.x * TPB + threadIdx.x;
    int xp = id & 63;
    int y  = (id >> 6) & 127;
    int p  = id >> 13;
    int b  = p / 3, co = p % 3;

    float2 s = make_float2(0.f, 0.f);
#pragma unroll
    for (int h = 0; h < 4; h++) {
        float2 v = reinterpret_cast<const float2*>(g_part[h])[id];
        s.x += v.x; s.y += v.y;
    }
    float bs = bias[co];

    const float* sk = skip + ((size_t)b * 3 + co) * 64 * 64;
    int syn = y >> 1;
    int syf = (y & 1) ? syn + 1 : syn - 1;
    float wyf = (syf >= 0 && syf < 64) ? 0.25f : 0.0f;
    int syfc = min(63, max(0, syf));
    const float* rn = sk + syn * 64;
    const float* rf = sk + syfc * 64;
    float cl_n = (xp > 0)  ? rn[xp - 1] : 0.f;
    float cc_n = rn[xp];
    float cr_n = (xp < 63) ? rn[xp + 1] : 0.f;
    float cl_f = (xp > 0)  ? rf[xp - 1] : 0.f;
    float cc_f = rf[xp];
    float cr_f = (xp < 63) ? rf[xp + 1] : 0.f;
    float rnx0 = 0.75f * cc_n + 0.25f * cl_n;
    float rnx1 = 0.75f * cc_n + 0.25f * cr_n;
    float rfx0 = 0.75f * cc_f + 0.25f * cl_f;
    float rfx1 = 0.75f * cc_f + 0.25f * cr_f;
    float sx0 = 0.75f * rnx0 + wyf * rfx0;
    float sx1 = 0.75f * rnx1 + wyf * rfx1;

    float2 o;
    o.x = s.x + bs + sx0;
    o.y = s.y + bs + sx1;
    reinterpret_cast<float2*>(out)[id] = o;
}

extern "C" void kernel_launch(void* const* d_in, const int* in_sizes, int n_in,
                              void* d_out, int out_size)
{
    const float* input  = (const float*)d_in[0];
    const float* skip   = (const float*)d_in[1];
    const float* weight = (const float*)d_in[2];
    const float* bias   = (const float*)d_in[3];
    float* out = (float*)d_out;

    cudaFuncSetAttribute(conv_kernel,
                         cudaFuncAttributeMaxDynamicSharedMemorySize, SMEM_BYTES);

    prep_kernel<<<(C_IN * WCH_ULL + TPB - 1) / TPB, TPB>>>(weight);
    dim3 grid(16, 8, 4);
    conv_kernel<<<grid, TPB, SMEM_BYTES>>>(input);
    epilogue_kernel<<<(8 * 3 * HW * HW / 2) / TPB, TPB>>>(skip, bias, out);
}

// round 9
// speedup vs baseline: 1.1545x; 1.0318x over previous
#include <cuda_runtime.h>
#include <cstdint>

// ToRGB split-K conv + epilogue, R9.
// k1: conv, grid (8,8,4): 4px-wide threads (32x8), 16-row tiles, 2-stage cp.async ring.
// k0: weight prep; k2: epilogue; k3: dummy (shifts ncu capture onto conv).

using ull = unsigned long long;

constexpr int TPB      = 256;
constexpr int HW       = 128;
constexpr int C_IN     = 512;
constexpr int C_PER    = 128;
constexpr int CPS      = 4;
constexpr int NSTAGE   = 2;
constexpr int NITER    = C_PER / CPS;                  // 32
constexpr int TILE_W   = 136;                          // idx = col + 4; zeros 0..3, 132..135
constexpr int TILE_ROWS= 18;                           // y0-1 .. y0+16
constexpr int TILE_FLOATS = TILE_ROWS * TILE_W;        // 2448
constexpr int DATA_BYTES  = CPS * TILE_FLOATS * 4;     // 39168
constexpr int WCH_ULL     = 32;
constexpr int WSTAGE_BYTES= CPS * WCH_ULL * 8;         // 1024
constexpr int STAGE_BYTES = DATA_BYTES + WSTAGE_BYTES; // 40192
constexpr unsigned SMEM_BYTES = NSTAGE * STAGE_BYTES;  // 80384
constexpr int NDATA    = CPS * TILE_ROWS * 32;         // 2304 (32 16B chunks/row)
constexpr int NCHUNK   = NDATA + CPS * 16;             // 2368
constexpr int JMAX     = (NCHUNK + TPB - 1) / TPB;     // 10

__device__ __align__(16) ull g_wdup[C_IN * WCH_ULL];
__device__ float g_part[4][8 * 3 * HW * HW];

__device__ __forceinline__ ull pack2(float lo, float hi) {
    ull r; asm("mov.b64 %0, {%1,%2};" : "=l"(r) : "f"(lo), "f"(hi)); return r;
}
__device__ __forceinline__ void unpack2(ull v, float& lo, float& hi) {
    asm("mov.b64 {%0,%1}, %2;" : "=f"(lo), "=f"(hi) : "l"(v));
}
__device__ __forceinline__ void ffma2(ull& d, ull a, ull b) {
    asm("fma.rn.f32x2 %0, %1, %2, %0;" : "+l"(d) : "l"(a), "l"(b));
}
__device__ __forceinline__ void cp16(uint32_t dst, const void* src, int ssz) {
    asm volatile("cp.async.cg.shared.global [%0], [%1], 16, %2;"
                 :: "r"(dst), "l"(src), "r"(ssz) : "memory");
}
__device__ __forceinline__ void cp_commit() {
    asm volatile("cp.async.commit_group;" ::: "memory");
}
template<int N> __device__ __forceinline__ void cp_wait() {
    asm volatile("cp.async.wait_group %0;" :: "n"(N) : "memory");
}

// ---------------- k0: weight prep ----------------
__global__ void prep_kernel(const float* __restrict__ weight)
{
    int i = blockIdx.x * TPB + threadIdx.x;
    if (i >= C_IN * WCH_ULL) return;
    int c = i / WCH_ULL, slot = i % WCH_ULL;
    int co = slot / 10, k = slot % 10;
    float w = 0.f;
    if (co < 3 && k < 9)
        w = weight[(co * C_IN + c) * 9 + k] * (1.0f / sqrtf(4608.0f));
    g_wdup[i] = pack2(w, w);
}

// ---------------- k1: split-K conv ----------------
__global__ void __launch_bounds__(TPB, 2)
conv_kernel(const float* __restrict__ input)
{
    extern __shared__ char smem_raw[];
    float* tiles = reinterpret_cast<float*>(smem_raw);

    const int tid = threadIdx.x;
    const int tx4 = tid & 31;          // x-quad: pixels 4*tx4 .. 4*tx4+3
    const int tyg = tid >> 5;          // 0..7: out rows y0 + 2*tyg + {0,1}
    const int b   = blockIdx.y;
    const int y0  = blockIdx.x * 16;
    const int qh  = blockIdx.z;
    const int cbase = qh * C_PER;

    // zero halo cols (idx 0..3, 132..135) for every (stage, ch, row)
    for (int i = tid; i < NSTAGE * CPS * TILE_ROWS; i += TPB) {
        float* row = tiles + (i / (CPS * TILE_ROWS)) * (STAGE_BYTES / 4)
                   + (i % (CPS * TILE_ROWS)) * TILE_W;
        *reinterpret_cast<float4*>(row)       = make_float4(0.f, 0.f, 0.f, 0.f);
        *reinterpret_cast<float4*>(row + 132) = make_float4(0.f, 0.f, 0.f, 0.f);
    }

    uint32_t tiles_u32 = (uint32_t)__cvta_generic_to_shared(tiles);
    int dsto[JMAX], boff[JMAX], ssz[JMAX];
    bool isw[JMAX], act[JMAX];
#pragma unroll
    for (int j = 0; j < JMAX; j++) {
        int g = j * TPB + tid;
        act[j] = (g < NCHUNK);
        isw[j] = false; dsto[j] = 0; boff[j] = 0; ssz[j] = 0;
        if (g < NDATA) {
            int ch  = g / (TILE_ROWS * 32);
            int rem = g - ch * (TILE_ROWS * 32);
            int row = rem >> 5;
            int c4  = rem & 31;
            int y   = y0 - 1 + row;
            bool ok = (y >= 0) && (y < HW);
            dsto[j] = ch * (TILE_FLOATS * 4) + row * (TILE_W * 4) + 16 + c4 * 16;
            boff[j] = ch * (HW * HW * 4) + (ok ? y : 0) * (HW * 4) + c4 * 16;
            ssz[j]  = ok ? 16 : 0;
        } else if (act[j]) {
            int wq = g - NDATA;
            int ch = wq >> 4, p = wq & 15;
            dsto[j] = DATA_BYTES + ch * 256 + p * 16;
            boff[j] = ch * 256 + p * 16;
            ssz[j]  = 16;
            isw[j]  = true;
        }
    }
    const char* in_b = reinterpret_cast<const char*>(input) + (size_t)b * C_IN * HW * HW * 4;
    const char* wgl  = reinterpret_cast<const char*>(g_wdup);

    __syncthreads();   // halo zeros visible

    // prologue: fill stage 0
    {
        const char* db = in_b + (size_t)cbase * (HW * HW * 4);
        const char* wb = wgl + (size_t)cbase * 256;
#pragma unroll
        for (int j = 0; j < JMAX; j++)
            if (act[j]) cp16(tiles_u32 + dsto[j], (isw[j] ? wb : db) + boff[j], ssz[j]);
        cp_commit();
    }

    ull acc[12];   // [(co*2+dy)*2 + half]
#pragma unroll
    for (int i = 0; i < 12; i++) acc[i] = 0ull;

    const int trow0 = tyg * 2;
    for (int it = 0; it < NITER; it++) {
        cp_wait<0>();
        __syncthreads();   // stage it&1 ready; all warps done with stage (it-1)&1

        int nc = it + 1;
        if (nc < NITER) {
            uint32_t sb = tiles_u32 + (nc & 1) * STAGE_BYTES;
            int bc = cbase + nc * CPS;
            const char* db = in_b + (size_t)bc * (HW * HW * 4);
            const char* wb = wgl + (size_t)bc * 256;
#pragma unroll
            for (int j = 0; j < JMAX; j++)
                if (act[j]) cp16(sb + dsto[j], (isw[j] ? wb : db) + boff[j], ssz[j]);
        }
        cp_commit();

        const float* st = tiles + (it & 1) * (STAGE_BYTES / 4);
#pragma unroll
        for (int ci = 0; ci < CPS; ci++) {
            const float* tp = st + ci * TILE_FLOATS + trow0 * TILE_W;
            // per row: taps for 4 px -> 6 ulls (A0,A1 | P0,P1 | C0,C1), C0==A1
            ull A0[4], A1[4], P0[4], P1[4], C1[4];
#pragma unroll
            for (int r = 0; r < 4; r++) {
                const float* rp = tp + r * TILE_W;
                float s  = rp[4 * tx4 + 3];
                ulonglong2 cc = *reinterpret_cast<const ulonglong2*>(rp + 4 * tx4 + 4);
                float rr = rp[4 * tx4 + 8];
                float c0, c1, c2, c3;
                unpack2(cc.x, c0, c1);
                unpack2(cc.y, c2, c3);
                P0[r] = cc.x;  P1[r] = cc.y;
                A0[r] = pack2(s,  c0);
                A1[r] = pack2(c1, c2);
                C1[r] = pack2(c3, rr);
            }
            const ulonglong2* wch = reinterpret_cast<const ulonglong2*>(
                reinterpret_cast<const char*>(st) + DATA_BYTES + ci * 256);
#pragma unroll
            for (int co = 0; co < 3; co++) {
                ulonglong2 p0 = wch[co * 5 + 0];
                ulonglong2 p1 = wch[co * 5 + 1];
                ulonglong2 p2 = wch[co * 5 + 2];
                ulonglong2 p3 = wch[co * 5 + 3];
                ulonglong2 p4 = wch[co * 5 + 4];
                ull wk[9] = { p0.x, p0.y, p1.x, p1.y, p2.x, p2.y, p3.x, p3.y, p4.x };
#pragma unroll
                for (int ky = 0; ky < 3; ky++)
#pragma unroll
                    for (int dy = 0; dy < 2; dy++) {
                        int r = dy + ky;
                        ull* a = &acc[(co * 2 + dy) * 2];
                        ffma2(a[0], wk[ky * 3 + 0], A0[r]);
                        ffma2(a[1], wk[ky * 3 + 0], A1[r]);
                        ffma2(a[0], wk[ky * 3 + 1], P0[r]);
                        ffma2(a[1], wk[ky * 3 + 1], P1[r]);
                        ffma2(a[0], wk[ky * 3 + 2], A1[r]);   // C0 == A1
                        ffma2(a[1], wk[ky * 3 + 2], C1[r]);
                    }
            }
        }
    }
    cp_wait<0>();

#pragma unroll
    for (int co = 0; co < 3; co++)
#pragma unroll
        for (int dy = 0; dy < 2; dy++) {
            int y = y0 + tyg * 2 + dy;
            float l0, h0, l1, h1;
            unpack2(acc[(co * 2 + dy) * 2 + 0], l0, h0);
            unpack2(acc[(co * 2 + dy) * 2 + 1], l1, h1);
            float4 o; o.x = l0; o.y = h0; o.z = l1; o.w = h1;
            *reinterpret_cast<float4*>(
                &g_part[qh][(((size_t)(b * 3 + co) * HW + y) * HW) + 4 * tx4]) = o;
        }
}

// ---------------- k2: epilogue ----------------
__global__ void __launch_bounds__(TPB)
epilogue_kernel(const float* __restrict__ skip, const float* __restrict__ bias,
                float* __restrict__ out)
{
    int id = blockIdx.x * TPB + threadIdx.x;
    int xp = id & 63;
    int y  = (id >> 6) & 127;
    int p  = id >> 13;
    int b  = p / 3, co = p % 3;

    float2 s = make_float2(0.f, 0.f);
#pragma unroll
    for (int h = 0; h < 4; h++) {
        float2 v = reinterpret_cast<const float2*>(g_part[h])[id];
        s.x += v.x; s.y += v.y;
    }
    float bs = bias[co];

    const float* sk = skip + ((size_t)b * 3 + co) * 64 * 64;
    int syn = y >> 1;
    int syf = (y & 1) ? syn + 1 : syn - 1;
    float wyf = (syf >= 0 && syf < 64) ? 0.25f : 0.0f;
    int syfc = min(63, max(0, syf));
    const float* rn = sk + syn * 64;
    const float* rf = sk + syfc * 64;
    float cl_n = (xp > 0)  ? rn[xp - 1] : 0.f;
    float cc_n = rn[xp];
    float cr_n = (xp < 63) ? rn[xp + 1] : 0.f;
    float cl_f = (xp > 0)  ? rf[xp - 1] : 0.f;
    float cc_f = rf[xp];
    float cr_f = (xp < 63) ? rf[xp + 1] : 0.f;
    float rnx0 = 0.75f * cc_n + 0.25f * cl_n;
    float rnx1 = 0.75f * cc_n + 0.25f * cr_n;
    float rfx0 = 0.75f * cc_f + 0.25f * cl_f;
    float rfx1 = 0.75f * cc_f + 0.25f * cr_f;
    float sx0 = 0.75f * rnx0 + wyf * rfx0;
    float sx1 = 0.75f * rnx1 + wyf * rfx1;

    float2 o;
    o.x = s.x + bs + sx0;
    o.y = s.y + bs + sx1;
    reinterpret_cast<float2*>(out)[id] = o;
}

// ---------------- k3: dummy (aligns ncu -s 5 capture onto conv) ----------------
__global__ void dummy_kernel() {}

extern "C" void kernel_launch(void* const* d_in, const int* in_sizes, int n_in,
                              void* d_out, int out_size)
{
    const float* input  = (const float*)d_in[0];
    const float* skip   = (const float*)d_in[1];
    const float* weight = (const float*)d_in[2];
    const float* bias   = (const float*)d_in[3];
    float* out = (float*)d_out;

    cudaFuncSetAttribute(conv_kernel,
                         cudaFuncAttributeMaxDynamicSharedMemorySize, SMEM_BYTES);

    prep_kernel<<<(C_IN * WCH_ULL + TPB - 1) / TPB, TPB>>>(weight);
    dim3 grid(8, 8, 4);
    conv_kernel<<<grid, TPB, SMEM_BYTES>>>(input);
    epilogue_kernel<<<(8 * 3 * HW * HW / 2) / TPB, TPB>>>(skip, bias, out);
    dummy_kernel<<<1, 1>>>();
}

// round 10
// speedup vs baseline: 1.3331x; 1.1547x over previous
#include <cuda_runtime.h>
#include <cstdint>

// ToRGB split-K conv + epilogue, R10.
// Key change vs R9: cp.async (16B, LSU rt=8cyc -> ~2.25TB/s chip cap) replaced by
// cp.async.bulk 512B row copies with mbarrier complete_tx (async proxy, LTS-rate).
// k1: conv, grid (8,8,4): 4px-wide threads (32x8), 16-row tiles, 2-stage mbarrier ring.

using ull = unsigned long long;

constexpr int TPB      = 256;
constexpr int HW       = 128;
constexpr int C_IN     = 512;
constexpr int C_PER    = 128;
constexpr int CPS      = 4;
constexpr int NSTAGE   = 2;
constexpr int NITER    = C_PER / CPS;                  // 32
constexpr int TILE_W   = 136;                          // idx = col + 4; zeros 0..3, 132..135
constexpr int TILE_ROWS= 18;                           // y0-1 .. y0+16
constexpr int TILE_FLOATS = TILE_ROWS * TILE_W;        // 2448
constexpr int CH_BYTES    = TILE_FLOATS * 4;           // 9792
constexpr int DATA_BYTES  = CPS * CH_BYTES;            // 39168
constexpr int WCH_ULL     = 32;
constexpr int WSTAGE_BYTES= CPS * WCH_ULL * 8;         // 1024
constexpr int STAGE_BYTES = DATA_BYTES + WSTAGE_BYTES; // 40192
constexpr unsigned MBAR_OFF   = NSTAGE * STAGE_BYTES;  // 80384
constexpr unsigned SMEM_BYTES = MBAR_OFF + 64;

__device__ __align__(16) ull g_wdup[C_IN * WCH_ULL];
__device__ float g_part[4][8 * 3 * HW * HW];

__device__ __forceinline__ ull pack2(float lo, float hi) {
    ull r; asm("mov.b64 %0, {%1,%2};" : "=l"(r) : "f"(lo), "f"(hi)); return r;
}
__device__ __forceinline__ void unpack2(ull v, float& lo, float& hi) {
    asm("mov.b64 {%0,%1}, %2;" : "=f"(lo), "=f"(hi) : "l"(v));
}
__device__ __forceinline__ void ffma2(ull& d, ull a, ull b) {
    asm("fma.rn.f32x2 %0, %1, %2, %0;" : "+l"(d) : "l"(a), "l"(b));
}
__device__ __forceinline__ void bulk_cp(uint32_t dst, const void* src, uint32_t bytes,
                                        uint32_t mbar) {
    asm volatile("cp.async.bulk.shared::cluster.global.mbarrier::complete_tx::bytes "
                 "[%0], [%1], %2, [%3];"
                 :: "r"(dst), "l"(src), "r"(bytes), "r"(mbar) : "memory");
}
__device__ __forceinline__ void mbar_init(uint32_t mbar, uint32_t cnt) {
    asm volatile("mbarrier.init.shared.b64 [%0], %1;" :: "r"(mbar), "r"(cnt) : "memory");
}
__device__ __forceinline__ void mbar_expect_tx(uint32_t mbar, uint32_t bytes) {
    asm volatile("mbarrier.arrive.expect_tx.shared.b64 _, [%0], %1;"
                 :: "r"(mbar), "r"(bytes) : "memory");
}
__device__ __forceinline__ void mbar_wait(uint32_t mbar, uint32_t parity) {
    asm volatile(
        "{\n\t"
        ".reg .pred P;\n\t"
        "WAIT_%=:\n\t"
        "mbarrier.try_wait.parity.acquire.cta.shared::cta.b64 P, [%0], %1, 0x989680;\n\t"
        "@P bra.uni DONE_%=;\n\t"
        "bra.uni WAIT_%=;\n\t"
        "DONE_%=:\n\t"
        "}" :: "r"(mbar), "r"(parity) : "memory");
}

// ---------------- k0: weight prep ----------------
__global__ void prep_kernel(const float* __restrict__ weight)
{
    int i = blockIdx.x * TPB + threadIdx.x;
    if (i >= C_IN * WCH_ULL) return;
    int c = i / WCH_ULL, slot = i % WCH_ULL;
    int co = slot / 10, k = slot % 10;
    float w = 0.f;
    if (co < 3 && k < 9)
        w = weight[(co * C_IN + c) * 9 + k] * (1.0f / sqrtf(4608.0f));
    g_wdup[i] = pack2(w, w);
}

// ---------------- k1: split-K conv ----------------
__global__ void __launch_bounds__(TPB, 2)
conv_kernel(const float* __restrict__ input)
{
    extern __shared__ char smem_raw[];
    float* tiles = reinterpret_cast<float*>(smem_raw);

    const int tid = threadIdx.x;
    const int tx4 = tid & 31;          // x-quad: pixels 4*tx4 .. 4*tx4+3
    const int tyg = tid >> 5;          // 0..7: out rows y0 + 2*tyg + {0,1}
    const int b   = blockIdx.y;
    const int y0  = blockIdx.x * 16;
    const int qh  = blockIdx.z;
    const int cbase = qh * C_PER;

    uint32_t tiles_u32 = (uint32_t)__cvta_generic_to_shared(tiles);
    uint32_t mbar_u32  = tiles_u32 + MBAR_OFF;

    // zero the whole ring once (halo cols + possible OOB rows stay zero forever:
    // bulk ops only ever write bytes [16,528) of valid row slots)
    for (int i = tid; i < (int)(NSTAGE * STAGE_BYTES / 16); i += TPB)
        reinterpret_cast<float4*>(smem_raw)[i] = make_float4(0.f, 0.f, 0.f, 0.f);
    if (tid == 0) { mbar_init(mbar_u32, 1); mbar_init(mbar_u32 + 8, 1); }
    __syncthreads();

    const char* in_b = reinterpret_cast<const char*>(input) + (size_t)b * C_IN * HW * HW * 4;
    const char* wgl  = reinterpret_cast<const char*>(g_wdup);

    // per-CTA valid-row count (uniform): rows y0-1..y0+16 clipped to [0,128)
    const int  vrows = TILE_ROWS - (y0 == 0 ? 1 : 0) - (y0 == 112 ? 1 : 0);
    const uint32_t stage_tx = (uint32_t)(CPS * vrows * 512 + WSTAGE_BYTES);

    // my bulk-copy role (fixed per thread): tid<72 -> (ch,row) data; tid==72 -> weights
    const int my_ch  = tid / TILE_ROWS;            // valid for tid<72
    const int my_row = tid - my_ch * TILE_ROWS;
    const int my_y   = y0 - 1 + my_row;
    const bool my_data = (tid < CPS * TILE_ROWS) && (my_y >= 0) && (my_y < HW);

    auto issue_stage = [&](int nc) {
        int s = nc & 1;
        uint32_t sb = tiles_u32 + s * STAGE_BYTES;
        uint32_t mb = mbar_u32 + s * 8;
        int bc = cbase + nc * CPS;
        if (tid == 0) mbar_expect_tx(mb, stage_tx);
        if (my_data)
            bulk_cp(sb + my_ch * CH_BYTES + my_row * (TILE_W * 4) + 16,
                    in_b + (size_t)(bc + my_ch) * (HW * HW * 4) + (size_t)my_y * (HW * 4),
                    512, mb);
        else if (tid == CPS * TILE_ROWS)
            bulk_cp(sb + DATA_BYTES, wgl + (size_t)bc * 256, WSTAGE_BYTES, mb);
    };

    // prologue: fill both stages
    issue_stage(0);
    issue_stage(1);

    ull acc[12];
#pragma unroll
    for (int i = 0; i < 12; i++) acc[i] = 0ull;

    const int trow0 = tyg * 2;
    for (int it = 0; it < NITER; it++) {
        mbar_wait(mbar_u32 + (it & 1) * 8, (it >> 1) & 1);

        const float* st = tiles + (it & 1) * (STAGE_BYTES / 4);
#pragma unroll
        for (int ci = 0; ci < CPS; ci++) {
            const float* tp = st + ci * TILE_FLOATS + trow0 * TILE_W;
            ull A0[4], A1[4], P0[4], P1[4], C1[4];
#pragma unroll
            for (int r = 0; r < 4; r++) {
                const float* rp = tp + r * TILE_W;
                float s  = rp[4 * tx4 + 3];
                ulonglong2 cc = *reinterpret_cast<const ulonglong2*>(rp + 4 * tx4 + 4);
                float rr = rp[4 * tx4 + 8];
                float c0, c1, c2, c3;
                unpack2(cc.x, c0, c1);
                unpack2(cc.y, c2, c3);
                P0[r] = cc.x;  P1[r] = cc.y;
                A0[r] = pack2(s,  c0);
                A1[r] = pack2(c1, c2);
                C1[r] = pack2(c3, rr);
            }
            const ulonglong2* wch = reinterpret_cast<const ulonglong2*>(
                reinterpret_cast<const char*>(st) + DATA_BYTES + ci * 256);
#pragma unroll
            for (int co = 0; co < 3; co++) {
                ulonglong2 p0 = wch[co * 5 + 0];
                ulonglong2 p1 = wch[co * 5 + 1];
                ulonglong2 p2 = wch[co * 5 + 2];
                ulonglong2 p3 = wch[co * 5 + 3];
                ulonglong2 p4 = wch[co * 5 + 4];
                ull wk[9] = { p0.x, p0.y, p1.x, p1.y, p2.x, p2.y, p3.x, p3.y, p4.x };
#pragma unroll
                for (int ky = 0; ky < 3; ky++)
#pragma unroll
                    for (int dy = 0; dy < 2; dy++) {
                        int r = dy + ky;
                        ull* a = &acc[(co * 2 + dy) * 2];
                        ffma2(a[0], wk[ky * 3 + 0], A0[r]);
                        ffma2(a[1], wk[ky * 3 + 0], A1[r]);
                        ffma2(a[0], wk[ky * 3 + 1], P0[r]);
                        ffma2(a[1], wk[ky * 3 + 1], P1[r]);
                        ffma2(a[0], wk[ky * 3 + 2], A1[r]);   // C0 == A1
                        ffma2(a[1], wk[ky * 3 + 2], C1[r]);
                    }
            }
        }
        __syncthreads();                 // all warps done reading stage it&1
        if (it + 2 < NITER) issue_stage(it + 2);
    }

#pragma unroll
    for (int co = 0; co < 3; co++)
#pragma unroll
        for (int dy = 0; dy < 2; dy++) {
            int y = y0 + tyg * 2 + dy;
            float l0, h0, l1, h1;
            unpack2(acc[(co * 2 + dy) * 2 + 0], l0, h0);
            unpack2(acc[(co * 2 + dy) * 2 + 1], l1, h1);
            float4 o; o.x = l0; o.y = h0; o.z = l1; o.w = h1;
            *reinterpret_cast<float4*>(
                &g_part[qh][(((size_t)(b * 3 + co) * HW + y) * HW) + 4 * tx4]) = o;
        }
}

// ---------------- k2: epilogue ----------------
__global__ void __launch_bounds__(TPB)
epilogue_kernel(const float* __restrict__ skip, const float* __restrict__ bias,
                float* __restrict__ out)
{
    int id = blockIdx.x * TPB + threadIdx.x;
    int xp = id & 63;
    int y  = (id >> 6) & 127;
    int p  = id >> 13;
    int b  = p / 3, co = p % 3;

    float2 s = make_float2(0.f, 0.f);
#pragma unroll
    for (int h = 0; h < 4; h++) {
        float2 v = reinterpret_cast<const float2*>(g_part[h])[id];
        s.x += v.x; s.y += v.y;
    }
    float bs = bias[co];

    const float* sk = skip + ((size_t)b * 3 + co) * 64 * 64;
    int syn = y >> 1;
    int syf = (y & 1) ? syn + 1 : syn - 1;
    float wyf = (syf >= 0 && syf < 64) ? 0.25f : 0.0f;
    int syfc = min(63, max(0, syf));
    const float* rn = sk + syn * 64;
    const float* rf = sk + syfc * 64;
    float cl_n = (xp > 0)  ? rn[xp - 1] : 0.f;
    float cc_n = rn[xp];
    float cr_n = (xp < 63) ? rn[xp + 1] : 0.f;
    float cl_f = (xp > 0)  ? rf[xp - 1] : 0.f;
    float cc_f = rf[xp];
    float cr_f = (xp < 63) ? rf[xp + 1] : 0.f;
    float rnx0 = 0.75f * cc_n + 0.25f * cl_n;
    float rnx1 = 0.75f * cc_n + 0.25f * cr_n;
    float rfx0 = 0.75f * cc_f + 0.25f * cl_f;
    float rfx1 = 0.75f * cc_f + 0.25f * cr_f;
    float sx0 = 0.75f * rnx0 + wyf * rfx0;
    float sx1 = 0.75f * rnx1 + wyf * rfx1;

    float2 o;
    o.x = s.x + bs + sx0;
    o.y = s.y + bs + sx1;
    reinterpret_cast<float2*>(out)[id] = o;
}

extern "C" void kernel_launch(void* const* d_in, const int* in_sizes, int n_in,
                              void* d_out, int out_size)
{
    const float* input  = (const float*)d_in[0];
    const float* skip   = (const float*)d_in[1];
    const float* weight = (const float*)d_in[2];
    const float* bias   = (const float*)d_in[3];
    float* out = (float*)d_out;

    cudaFuncSetAttribute(conv_kernel,
                         cudaFuncAttributeMaxDynamicSharedMemorySize, SMEM_BYTES);

    prep_kernel<<<(C_IN * WCH_ULL + TPB - 1) / TPB, TPB>>>(weight);
    dim3 grid(8, 8, 4);
    conv_kernel<<<grid, TPB, SMEM_BYTES>>>(input);
    epilogue_kernel<<<(8 * 3 * HW * HW / 2) / TPB, TPB>>>(skip, bias, out);
}